// round 9
// baseline (speedup 1.0000x reference)
#include <cuda_runtime.h>
#include <cuda_bf16.h>

// ---------------- problem constants ----------------
#define NL   12
#define CC   1024
#define TT   512
#define NH   16
#define HD   64
#define FF   4096
#define BT   2048            // B*T
#define VV   32000
#define BH   64              // B*NH
#define QKVLD 3072           // fused qkv leading dim

// ---------------- GEMM tile config ----------------
#define BM 128
#define BN 128
#define BK 32
#define NSTAGE 3
#define A_STRIDE 80                        // 32 bf16 = 64B + 16B pad
#define B_STRIDE 272                       // 128 bf16 = 256B + 16B pad
#define OFF_AH 0
#define OFF_AL (128 * A_STRIDE)
#define OFF_BH (2 * 128 * A_STRIDE)
#define OFF_BL (OFF_BH + 32 * B_STRIDE)
#define STAGE_BYTES (OFF_BL + 32 * B_STRIDE)   // 37888
#define GEMM_SMEM (NSTAGE * STAGE_BYTES)       // 113664

// ---------------- split-weight layout (elements) ----------------
#define WSZ   (12ull * 1024 * 1024)
#define W1SZ  (12ull * 1024 * 4096)
#define WO_OFF   (3ull * WSZ)
#define W1_OFF   (WO_OFF + WSZ)
#define W2_OFF   (W1_OFF + W1SZ)
#define WLM_OFF  (W2_OFF + W1SZ)
#define WTOT     (WLM_OFF + 1024ull * 32000)

// ---------------- attention smem layout ----------------
#define QS 144
#define AT_QH 0
#define AT_QL 18432
#define AT_KH 36864
#define AT_KL 55296
#define AT_VH 73728
#define AT_VL 92160
#define ATTN_SMEM 110592

// ---------------- static device scratch ----------------
__device__ float g_x[BT * CC];
__device__ __nv_bfloat16 g_xnh [BT * CC],    g_xnl [BT * CC];
__device__ __nv_bfloat16 g_qkvh[BT * QKVLD], g_qkvl[BT * QKVLD];
__device__ __nv_bfloat16 g_yh  [BT * CC],    g_yl  [BT * CC];
__device__ __nv_bfloat16 g_hh  [BT * FF],    g_hl  [BT * FF];
__device__ __nv_bfloat16 g_whi[WTOT], g_wlo[WTOT];

// ---------------- helpers ----------------
__device__ __forceinline__ unsigned pack_bf16(float x, float y)
{
    __nv_bfloat162 h = __floats2bfloat162_rn(x, y);
    return *reinterpret_cast<unsigned*>(&h);
}

__device__ __forceinline__ void split_pair(float x, float y, unsigned& hi, unsigned& lo)
{
    float hx = __bfloat162float(__float2bfloat16(x));
    float hy = __bfloat162float(__float2bfloat16(y));
    hi = pack_bf16(x, y);
    lo = pack_bf16(x - hx, y - hy);
}

__device__ __forceinline__ void cp16(unsigned dst, const void* src)
{
    asm volatile("cp.async.cg.shared.global [%0],[%1],16;" :: "r"(dst), "l"(src));
}

__device__ __forceinline__ void ldsm4(unsigned* r, unsigned a)
{
    asm volatile("ldmatrix.sync.aligned.m8n8.x4.shared.b16 {%0,%1,%2,%3},[%4];"
                 : "=r"(r[0]), "=r"(r[1]), "=r"(r[2]), "=r"(r[3]) : "r"(a));
}
__device__ __forceinline__ void ldsm4t(unsigned* r, unsigned a)
{
    asm volatile("ldmatrix.sync.aligned.m8n8.x4.trans.shared.b16 {%0,%1,%2,%3},[%4];"
                 : "=r"(r[0]), "=r"(r[1]), "=r"(r[2]), "=r"(r[3]) : "r"(a));
}
__device__ __forceinline__ void mma_bf16(float* d, const unsigned* a, unsigned b0, unsigned b1)
{
    asm volatile("mma.sync.aligned.m16n8k16.row.col.f32.bf16.bf16.f32 "
                 "{%0,%1,%2,%3},{%4,%5,%6,%7},{%8,%9},{%0,%1,%2,%3};"
                 : "+f"(d[0]), "+f"(d[1]), "+f"(d[2]), "+f"(d[3])
                 : "r"(a[0]), "r"(a[1]), "r"(a[2]), "r"(a[3]),
                   "r"(b0), "r"(b1));
}

// ---------------- weight split kernels ----------------
__global__ void split_w_kernel(const float* __restrict__ src,
                               __nv_bfloat16* __restrict__ hi,
                               __nv_bfloat16* __restrict__ lo,
                               int n4)
{
    int i = blockIdx.x * 256 + threadIdx.x;
    if (i >= n4) return;
    float4 v = ((const float4*)src)[i];
    unsigned h0, l0, h1, l1;
    split_pair(v.x, v.y, h0, l0);
    split_pair(v.z, v.w, h1, l1);
    ((uint2*)hi)[i] = make_uint2(h0, h1);
    ((uint2*)lo)[i] = make_uint2(l0, l1);
}

__global__ void split_w3_kernel(const float* __restrict__ src,
                                __nv_bfloat16* __restrict__ hi,
                                __nv_bfloat16* __restrict__ lo,
                                int cofs)
{
    long i = (long)blockIdx.x * 256 + threadIdx.x;
    long e = i * 4;
    long l  = e >> 20;
    long rm = e & 1048575;
    long kk = rm >> 10;
    long n  = rm & 1023;
    float4 v = ((const float4*)src)[i];
    unsigned h0, l0, h1, l1;
    split_pair(v.x, v.y, h0, l0);
    split_pair(v.z, v.w, h1, l1);
    long d = l * 3145728 + kk * 3072 + cofs + n;
    *(uint2*)(hi + d) = make_uint2(h0, h1);
    *(uint2*)(lo + d) = make_uint2(l0, l1);
}

// ---------------- embedding ----------------
__global__ void embed_kernel(const int* __restrict__ idx,
                             const float* __restrict__ tok,
                             const float* __restrict__ pos,
                             float* __restrict__ x)
{
    int row = blockIdx.x;
    int t   = row & (TT - 1);
    int id  = idx[row];
    int c   = threadIdx.x * 4;
    float4 tv = *(const float4*)(tok + (size_t)id * CC + c);
    float4 pv = *(const float4*)(pos + (size_t)t  * CC + c);
    float4 o;
    o.x = tv.x + pv.x; o.y = tv.y + pv.y; o.z = tv.z + pv.z; o.w = tv.w + pv.w;
    *(float4*)(x + (size_t)row * CC + c) = o;
}

// ---------------- layernorm -> split bf16 hi/lo ----------------
__global__ void ln_kernel(const float* __restrict__ x,
                          __nv_bfloat16* __restrict__ oh,
                          __nv_bfloat16* __restrict__ ol,
                          const float* __restrict__ g, const float* __restrict__ b)
{
    int row = blockIdx.x;
    int tid = threadIdx.x;
    const float* xr = x + (size_t)row * CC;
    float4 xv = *(const float4*)(xr + tid * 4);
    float s  = xv.x + xv.y + xv.z + xv.w;
    float s2 = xv.x*xv.x + xv.y*xv.y + xv.z*xv.z + xv.w*xv.w;
    #pragma unroll
    for (int off = 16; off > 0; off >>= 1) {
        s  += __shfl_xor_sync(0xffffffffu, s,  off);
        s2 += __shfl_xor_sync(0xffffffffu, s2, off);
    }
    __shared__ float sh[16];
    int w = tid >> 5;
    if ((tid & 31) == 0) { sh[w] = s; sh[8 + w] = s2; }
    __syncthreads();
    s = 0.f; s2 = 0.f;
    #pragma unroll
    for (int i = 0; i < 8; i++) { s += sh[i]; s2 += sh[8 + i]; }
    float mean = s * (1.0f / CC);
    float var  = s2 * (1.0f / CC) - mean * mean;
    float rinv = rsqrtf(var + 1e-5f);
    float4 gv = *(const float4*)(g + tid * 4);
    float4 bv = *(const float4*)(b + tid * 4);
    float4 ov;
    ov.x = (xv.x - mean) * rinv * gv.x + bv.x;
    ov.y = (xv.y - mean) * rinv * gv.y + bv.y;
    ov.z = (xv.z - mean) * rinv * gv.z + bv.z;
    ov.w = (xv.w - mean) * rinv * gv.w + bv.w;
    unsigned h0, l0, h1, l1;
    split_pair(ov.x, ov.y, h0, l0);
    split_pair(ov.z, ov.w, h1, l1);
    size_t o = (size_t)row * CC + tid * 4;
    *(uint2*)(oh + o) = make_uint2(h0, h1);
    *(uint2*)(ol + o) = make_uint2(l0, l1);
}

// ---------------- tensor-core GEMM: all operands pre-split bf16, cp.async ----
// EPI: 0 = fp32 out; 1 = split out (no bias); 2 = split out +bias,relu;
//      3 = fp32 out +bias +resid
template <int EPI>
__global__ __launch_bounds__(256)
void bgemm_kernel(int M, int N, int K,
                  const __nv_bfloat16* __restrict__ Ah_,
                  const __nv_bfloat16* __restrict__ Al_,
                  const __nv_bfloat16* __restrict__ Bh_,
                  const __nv_bfloat16* __restrict__ Bl_,
                  float* __restrict__ outF,
                  __nv_bfloat16* __restrict__ outH,
                  __nv_bfloat16* __restrict__ outL,
                  const float* __restrict__ bias,
                  const float* __restrict__ resid)
{
    extern __shared__ char smem[];
    const unsigned sbase = (unsigned)__cvta_generic_to_shared(smem);
    const int tid  = threadIdx.x;
    const int bm   = blockIdx.y * BM;
    const int bn   = blockIdx.x * BN;
    const int warp = tid >> 5, lane = tid & 31;
    const int wm   = warp >> 2, wn = warp & 3;

    // producer chunk mapping (16B chunks)
    const int ar  = tid >> 2;          // 0..63   (A rows ar, ar+64)
    const int ac8 = tid & 3;           // A col chunk
    const int br  = tid >> 4;          // 0..15   (B rows br, br+16)
    const int bc8 = tid & 15;          // B col chunk

    const size_t aBase0 = (size_t)(bm + ar) * K + ac8 * 8;
    const size_t aBase1 = (size_t)(bm + ar + 64) * K + ac8 * 8;

    auto prefetch = [&](int kt, int s) {
        const unsigned st = sbase + s * STAGE_BYTES;
        const int k0 = kt * BK;
        unsigned d = st + OFF_AH + ar * A_STRIDE + ac8 * 16;
        cp16(d,                 Ah_ + aBase0 + k0);
        cp16(d + 64 * A_STRIDE, Ah_ + aBase1 + k0);
        d = st + OFF_AL + ar * A_STRIDE + ac8 * 16;
        cp16(d,                 Al_ + aBase0 + k0);
        cp16(d + 64 * A_STRIDE, Al_ + aBase1 + k0);
        const size_t bb = (size_t)(k0 + br) * N + bn + bc8 * 8;
        d = st + OFF_BH + br * B_STRIDE + bc8 * 16;
        cp16(d,                 Bh_ + bb);
        cp16(d + 16 * B_STRIDE, Bh_ + bb + (size_t)16 * N);
        d = st + OFF_BL + br * B_STRIDE + bc8 * 16;
        cp16(d,                 Bl_ + bb);
        cp16(d + 16 * B_STRIDE, Bl_ + bb + (size_t)16 * N);
    };

    const int kTiles = K / BK;
    #pragma unroll
    for (int p = 0; p < NSTAGE - 1; p++) {
        prefetch(p, p);
        asm volatile("cp.async.commit_group;");
    }

    float acc[4][4][4];
    #pragma unroll
    for (int i = 0; i < 4; i++)
        #pragma unroll
        for (int j = 0; j < 4; j++)
            #pragma unroll
            for (int r = 0; r < 4; r++) acc[i][j][r] = 0.f;

    const int am   = wm * 64 + (lane & 15);
    const int aKof = (lane >> 4) << 3;
    const int bk   = lane & 15;
    const int nb   = wn * 32 + ((lane >> 4) << 3);

    for (int kt = 0; kt < kTiles; kt++) {
        asm volatile("cp.async.wait_group 1;");
        __syncthreads();
        int pf = kt + NSTAGE - 1;
        if (pf < kTiles) prefetch(pf, pf % NSTAGE);
        asm volatile("cp.async.commit_group;");

        const unsigned st = sbase + (kt % NSTAGE) * STAGE_BYTES;
        #pragma unroll
        for (int h = 0; h < 2; h++) {
            unsigned ah[4][4], al[4][4], bhf[2][4], blf[2][4];
            const int kc = h * 16 + aKof;
            #pragma unroll
            for (int i = 0; i < 4; i++) {
                unsigned arow_off = (unsigned)((am + i * 16) * A_STRIDE + kc * 2);
                ldsm4(ah[i], st + OFF_AH + arow_off);
                ldsm4(al[i], st + OFF_AL + arow_off);
            }
            const int bkh = h * 16 + bk;
            #pragma unroll
            for (int j = 0; j < 2; j++) {
                unsigned boff = (unsigned)(bkh * B_STRIDE + (nb + j * 16) * 2);
                ldsm4t(bhf[j], st + OFF_BH + boff);
                ldsm4t(blf[j], st + OFF_BL + boff);
            }
            #pragma unroll
            for (int i = 0; i < 4; i++) {
                #pragma unroll
                for (int jj = 0; jj < 4; jj++) {
                    const unsigned* ph = &bhf[jj >> 1][(jj & 1) * 2];
                    const unsigned* pl = &blf[jj >> 1][(jj & 1) * 2];
                    mma_bf16(acc[i][jj], ah[i], ph[0], ph[1]);
                    mma_bf16(acc[i][jj], al[i], ph[0], ph[1]);
                    mma_bf16(acc[i][jj], ah[i], pl[0], pl[1]);
                }
            }
        }
    }

    const int mrow = bm + wm * 64 + (lane >> 2);
    const int ncol = bn + wn * 32 + (lane & 3) * 2;
    #pragma unroll
    for (int i = 0; i < 4; i++) {
        #pragma unroll
        for (int jj = 0; jj < 4; jj++) {
            int r0 = mrow + i * 16;
            int c  = ncol + jj * 8;
            float2 v0 = make_float2(acc[i][jj][0], acc[i][jj][1]);
            float2 v1 = make_float2(acc[i][jj][2], acc[i][jj][3]);
            if (EPI == 2 || EPI == 3) {
                float b0v = bias[c], b1v = bias[c + 1];
                v0.x += b0v; v0.y += b1v; v1.x += b0v; v1.y += b1v;
            }
            if (EPI == 2) {
                v0.x = fmaxf(v0.x, 0.f); v0.y = fmaxf(v0.y, 0.f);
                v1.x = fmaxf(v1.x, 0.f); v1.y = fmaxf(v1.y, 0.f);
            }
            size_t o0 = (size_t)r0 * N + c;
            size_t o1 = (size_t)(r0 + 8) * N + c;
            if (EPI == 3) {
                float2 q0 = *(const float2*)(resid + o0);
                float2 q1 = *(const float2*)(resid + o1);
                v0.x += q0.x; v0.y += q0.y; v1.x += q1.x; v1.y += q1.y;
            }
            if (EPI == 0 || EPI == 3) {
                *(float2*)(outF + o0) = v0;
                *(float2*)(outF + o1) = v1;
            } else {
                unsigned h0, l0;
                split_pair(v0.x, v0.y, h0, l0);
                *(unsigned*)(outH + o0) = h0;
                *(unsigned*)(outL + o0) = l0;
                split_pair(v1.x, v1.y, h0, l0);
                *(unsigned*)(outH + o1) = h0;
                *(unsigned*)(outL + o1) = l0;
            }
        }
    }
}

// ---------------- fused flash attention (pre-split qkv in, split y out) ----
__global__ __launch_bounds__(256)
void attn_kernel(const __nv_bfloat16* __restrict__ qkvh,
                 const __nv_bfloat16* __restrict__ qkvl,
                 __nv_bfloat16* __restrict__ yh,
                 __nv_bfloat16* __restrict__ yl)
{
    extern __shared__ char sm[];
    const unsigned sb = (unsigned)__cvta_generic_to_shared(sm);
    const int qt   = blockIdx.x;
    const int bh   = blockIdx.y;
    const int b    = bh >> 4, h = bh & 15;
    const int tid  = threadIdx.x;
    const int warp = tid >> 5, lane = tid & 31;

    const int    qbase   = qt * 128;
    const size_t rowbase = (size_t)b * TT;
    const int    colh    = h * HD;

    // ---- load Q tile (hi+lo, direct bf16 copy) ----
    for (int i = tid; i < 1024; i += 256) {
        int r = i >> 3, c8 = i & 7;
        size_t g = (rowbase + qbase + r) * QKVLD + colh + c8 * 8;
        *(uint4*)(sm + AT_QH + r * QS + c8 * 16) = *(const uint4*)(qkvh + g);
        *(uint4*)(sm + AT_QL + r * QS + c8 * 16) = *(const uint4*)(qkvl + g);
    }
    __syncthreads();

    unsigned qh[4][4], ql[4][4];
    {
        int rr = warp * 16 + (lane & 15);
        int kc = (lane >> 4) << 3;
        #pragma unroll
        for (int ks = 0; ks < 4; ks++) {
            unsigned off = (unsigned)(rr * QS + (ks * 16 + kc) * 2);
            ldsm4(qh[ks], sb + AT_QH + off);
            ldsm4(ql[ks], sb + AT_QL + off);
        }
    }

    float Oc[8][4];
    #pragma unroll
    for (int f = 0; f < 8; f++)
        #pragma unroll
        for (int r = 0; r < 4; r++) Oc[f][r] = 0.f;
    float m0 = -1e30f, m8 = -1e30f, l0s = 0.f, l8s = 0.f;

    for (int jt = 0; jt <= qt; jt++) {
        const int jbase = jt * 128;
        __syncthreads();
        for (int i = tid; i < 1024; i += 256) {
            int r = i >> 3, c8 = i & 7;
            size_t g = (rowbase + jbase + r) * QKVLD + colh + c8 * 8;
            *(uint4*)(sm + AT_KH + r * QS + c8 * 16) = *(const uint4*)(qkvh + g + 1024);
            *(uint4*)(sm + AT_KL + r * QS + c8 * 16) = *(const uint4*)(qkvl + g + 1024);
            *(uint4*)(sm + AT_VH + r * QS + c8 * 16) = *(const uint4*)(qkvh + g + 2048);
            *(uint4*)(sm + AT_VL + r * QS + c8 * 16) = *(const uint4*)(qkvl + g + 2048);
        }
        __syncthreads();

        float s[16][4];
        #pragma unroll
        for (int f = 0; f < 16; f++)
            #pragma unroll
            for (int r = 0; r < 4; r++) s[f][r] = 0.f;

        #pragma unroll
        for (int ks = 0; ks < 4; ks++) {
            #pragma unroll
            for (int ng = 0; ng < 8; ng++) {
                unsigned off = (unsigned)((ng * 16 + (lane & 15)) * QS +
                                          (ks * 16 + ((lane >> 4) << 3)) * 2);
                unsigned kh4[4], kl4[4];
                ldsm4(kh4, sb + AT_KH + off);
                ldsm4(kl4, sb + AT_KL + off);
                mma_bf16(s[2*ng],   qh[ks], kh4[0], kh4[2]);
                mma_bf16(s[2*ng],   ql[ks], kh4[0], kh4[2]);
                mma_bf16(s[2*ng],   qh[ks], kl4[0], kl4[2]);
                mma_bf16(s[2*ng+1], qh[ks], kh4[1], kh4[3]);
                mma_bf16(s[2*ng+1], ql[ks], kh4[1], kh4[3]);
                mma_bf16(s[2*ng+1], qh[ks], kl4[1], kl4[3]);
            }
        }

        // scale by HD^-0.5 (exact power of two)
        #pragma unroll
        for (int f = 0; f < 16; f++) {
            s[f][0] *= 0.125f; s[f][1] *= 0.125f;
            s[f][2] *= 0.125f; s[f][3] *= 0.125f;
        }

        if (jt == qt) {
            int r0 = warp * 16 + (lane >> 2);
            #pragma unroll
            for (int f = 0; f < 16; f++) {
                int c = f * 8 + 2 * (lane & 3);
                if (c     > r0)     s[f][0] = -1e30f;
                if (c + 1 > r0)     s[f][1] = -1e30f;
                if (c     > r0 + 8) s[f][2] = -1e30f;
                if (c + 1 > r0 + 8) s[f][3] = -1e30f;
            }
        }

        float mx0 = -1e30f, mx8 = -1e30f;
        #pragma unroll
        for (int f = 0; f < 16; f++) {
            mx0 = fmaxf(mx0, fmaxf(s[f][0], s[f][1]));
            mx8 = fmaxf(mx8, fmaxf(s[f][2], s[f][3]));
        }
        mx0 = fmaxf(mx0, __shfl_xor_sync(0xffffffffu, mx0, 1));
        mx0 = fmaxf(mx0, __shfl_xor_sync(0xffffffffu, mx0, 2));
        mx8 = fmaxf(mx8, __shfl_xor_sync(0xffffffffu, mx8, 1));
        mx8 = fmaxf(mx8, __shfl_xor_sync(0xffffffffu, mx8, 2));
        float nm0 = fmaxf(m0, mx0), nm8 = fmaxf(m8, mx8);
        float a0 = __expf(m0 - nm0), a8 = __expf(m8 - nm8);

        float sum0 = 0.f, sum8 = 0.f;
        #pragma unroll
        for (int f = 0; f < 16; f++) {
            s[f][0] = __expf(s[f][0] - nm0);
            s[f][1] = __expf(s[f][1] - nm0);
            s[f][2] = __expf(s[f][2] - nm8);
            s[f][3] = __expf(s[f][3] - nm8);
            sum0 += s[f][0] + s[f][1];
            sum8 += s[f][2] + s[f][3];
        }
        sum0 += __shfl_xor_sync(0xffffffffu, sum0, 1);
        sum0 += __shfl_xor_sync(0xffffffffu, sum0, 2);
        sum8 += __shfl_xor_sync(0xffffffffu, sum8, 1);
        sum8 += __shfl_xor_sync(0xffffffffu, sum8, 2);
        l0s = l0s * a0 + sum0;
        l8s = l8s * a8 + sum8;
        m0 = nm0; m8 = nm8;
        #pragma unroll
        for (int f = 0; f < 8; f++) {
            Oc[f][0] *= a0; Oc[f][1] *= a0;
            Oc[f][2] *= a8; Oc[f][3] *= a8;
        }

        #pragma unroll
        for (int ks = 0; ks < 8; ks++) {
            unsigned ph[4], pl[4];
            split_pair(s[2*ks][0],   s[2*ks][1],   ph[0], pl[0]);
            split_pair(s[2*ks][2],   s[2*ks][3],   ph[1], pl[1]);
            split_pair(s[2*ks+1][0], s[2*ks+1][1], ph[2], pl[2]);
            split_pair(s[2*ks+1][2], s[2*ks+1][3], ph[3], pl[3]);
            #pragma unroll
            for (int ng = 0; ng < 4; ng++) {
                unsigned off = (unsigned)((ks * 16 + (lane & 15)) * QS +
                                          (ng * 16 + ((lane >> 4) << 3)) * 2);
                unsigned vh4[4], vl4[4];
                ldsm4t(vh4, sb + AT_VH + off);
                ldsm4t(vl4, sb + AT_VL + off);
                mma_bf16(Oc[2*ng],   ph, vh4[0], vh4[1]);
                mma_bf16(Oc[2*ng],   pl, vh4[0], vh4[1]);
                mma_bf16(Oc[2*ng],   ph, vl4[0], vl4[1]);
                mma_bf16(Oc[2*ng+1], ph, vh4[2], vh4[3]);
                mma_bf16(Oc[2*ng+1], pl, vh4[2], vh4[3]);
                mma_bf16(Oc[2*ng+1], ph, vl4[2], vl4[3]);
            }
        }
    }

    // ---- normalize + split store ----
    float i0 = 1.f / l0s, i8 = 1.f / l8s;
    int r0 = qbase + warp * 16 + (lane >> 2);
    #pragma unroll
    for (int f = 0; f < 8; f++) {
        int c = colh + f * 8 + 2 * (lane & 3);
        unsigned hh, ll;
        split_pair(Oc[f][0] * i0, Oc[f][1] * i0, hh, ll);
        *(unsigned*)(yh + (rowbase + r0) * CC + c) = hh;
        *(unsigned*)(yl + (rowbase + r0) * CC + c) = ll;
        split_pair(Oc[f][2] * i8, Oc[f][3] * i8, hh, ll);
        *(unsigned*)(yh + (rowbase + r0 + 8) * CC + c) = hh;
        *(unsigned*)(yl + (rowbase + r0 + 8) * CC + c) = ll;
    }
}

// ---------------- host launcher ----------------
template <typename T>
static T* sym_addr(const void* sym)
{
    void* p = nullptr;
    cudaGetSymbolAddress(&p, sym);
    return (T*)p;
}

extern "C" void kernel_launch(void* const* d_in, const int* in_sizes, int n_in,
                              void* d_out, int out_size)
{
    const int*   idx  = (const int*)  d_in[0];
    const float* tok  = (const float*)d_in[1];
    const float* pos  = (const float*)d_in[2];
    const float* wq   = (const float*)d_in[3];
    const float* wk   = (const float*)d_in[4];
    const float* wv   = (const float*)d_in[5];
    const float* wo   = (const float*)d_in[6];
    const float* bo   = (const float*)d_in[7];
    const float* ln1g = (const float*)d_in[8];
    const float* ln1b = (const float*)d_in[9];
    const float* ln2g = (const float*)d_in[10];
    const float* ln2b = (const float*)d_in[11];
    const float* w1   = (const float*)d_in[12];
    const float* b1   = (const float*)d_in[13];
    const float* w2   = (const float*)d_in[14];
    const float* b2   = (const float*)d_in[15];
    const float* lnfg = (const float*)d_in[16];
    const float* lnfb = (const float*)d_in[17];
    const float* wlm  = (const float*)d_in[18];
    float* out = (float*)d_out;

    float* x = sym_addr<float>(g_x);
    __nv_bfloat16* xnh  = sym_addr<__nv_bfloat16>(g_xnh);
    __nv_bfloat16* xnl  = sym_addr<__nv_bfloat16>(g_xnl);
    __nv_bfloat16* qkvh = sym_addr<__nv_bfloat16>(g_qkvh);
    __nv_bfloat16* qkvl = sym_addr<__nv_bfloat16>(g_qkvl);
    __nv_bfloat16* yh   = sym_addr<__nv_bfloat16>(g_yh);
    __nv_bfloat16* yl   = sym_addr<__nv_bfloat16>(g_yl);
    __nv_bfloat16* hh   = sym_addr<__nv_bfloat16>(g_hh);
    __nv_bfloat16* hl   = sym_addr<__nv_bfloat16>(g_hl);
    __nv_bfloat16* whi  = sym_addr<__nv_bfloat16>(g_whi);
    __nv_bfloat16* wlo  = sym_addr<__nv_bfloat16>(g_wlo);

    cudaFuncSetAttribute((const void*)bgemm_kernel<0>,
                         cudaFuncAttributeMaxDynamicSharedMemorySize, GEMM_SMEM);
    cudaFuncSetAttribute((const void*)bgemm_kernel<1>,
                         cudaFuncAttributeMaxDynamicSharedMemorySize, GEMM_SMEM);
    cudaFuncSetAttribute((const void*)bgemm_kernel<2>,
                         cudaFuncAttributeMaxDynamicSharedMemorySize, GEMM_SMEM);
    cudaFuncSetAttribute((const void*)bgemm_kernel<3>,
                         cudaFuncAttributeMaxDynamicSharedMemorySize, GEMM_SMEM);
    cudaFuncSetAttribute((const void*)attn_kernel,
                         cudaFuncAttributeMaxDynamicSharedMemorySize, ATTN_SMEM);

    split_w3_kernel<<<12288, 256>>>(wq, whi, wlo, 0);
    split_w3_kernel<<<12288, 256>>>(wk, whi, wlo, 1024);
    split_w3_kernel<<<12288, 256>>>(wv, whi, wlo, 2048);
    split_w_kernel<<<12288, 256>>>(wo,  whi + WO_OFF,  wlo + WO_OFF,  (int)(WSZ / 4));
    split_w_kernel<<<49152, 256>>>(w1,  whi + W1_OFF,  wlo + W1_OFF,  (int)(W1SZ / 4));
    split_w_kernel<<<49152, 256>>>(w2,  whi + W2_OFF,  wlo + W2_OFF,  (int)(W1SZ / 4));
    split_w_kernel<<<32000, 256>>>(wlm, whi + WLM_OFF, wlo + WLM_OFF, 8192000);

    embed_kernel<<<BT, 256>>>(idx, tok, pos, x);

    const dim3 gQkv (QKVLD / BN, BT / BM);  // (24,16)
    const dim3 gProj(CC / BN, BT / BM);     // (8,16)
    const dim3 gMlp1(FF / BN, BT / BM);     // (32,16)
    const dim3 gLm  (VV / BN, BT / BM);     // (250,16)
    const dim3 gAtt (4, BH);                // (4,64)

    for (int l = 0; l < NL; l++) {
        size_t o3 = (size_t)l * 3145728;
        size_t oo = WO_OFF + (size_t)l * 1048576;
        size_t o1 = W1_OFF + (size_t)l * 4194304;
        size_t o2 = W2_OFF + (size_t)l * 4194304;

        ln_kernel<<<BT, 256>>>(x, xnh, xnl, ln1g + l * CC, ln1b + l * CC);
        bgemm_kernel<1><<<gQkv, 256, GEMM_SMEM>>>(BT, QKVLD, CC, xnh, xnl,
                                                  whi + o3, wlo + o3,
                                                  nullptr, qkvh, qkvl, nullptr, nullptr);
        attn_kernel<<<gAtt, 256, ATTN_SMEM>>>(qkvh, qkvl, yh, yl);
        bgemm_kernel<3><<<gProj, 256, GEMM_SMEM>>>(BT, CC, CC, yh, yl,
                                                   whi + oo, wlo + oo,
                                                   x, nullptr, nullptr, bo + l * CC, x);
        ln_kernel<<<BT, 256>>>(x, xnh, xnl, ln2g + l * CC, ln2b + l * CC);
        bgemm_kernel<2><<<gMlp1, 256, GEMM_SMEM>>>(BT, FF, CC, xnh, xnl,
                                                   whi + o1, wlo + o1,
                                                   nullptr, hh, hl, b1 + l * FF, nullptr);
        bgemm_kernel<3><<<gProj, 256, GEMM_SMEM>>>(BT, CC, FF, hh, hl,
                                                   whi + o2, wlo + o2,
                                                   x, nullptr, nullptr, b2 + l * CC, x);
    }

    ln_kernel<<<BT, 256>>>(x, xnh, xnl, lnfg, lnfb);
    bgemm_kernel<0><<<gLm, 256, GEMM_SMEM>>>(BT, VV, CC, xnh, xnl,
                                             whi + WLM_OFF, wlo + WLM_OFF,
                                             out, nullptr, nullptr, nullptr, nullptr);
}

// round 13
// speedup vs baseline: 1.0633x; 1.0633x over previous
#include <cuda_runtime.h>
#include <cuda_bf16.h>

// ---------------- problem constants ----------------
#define NL   12
#define CC   1024
#define TT   512
#define NH   16
#define HD   64
#define FF   4096
#define BT   2048            // B*T
#define VV   32000
#define BH   64              // B*NH
#define QKVLD 3072           // fused qkv leading dim

// ---------------- GEMM tile config (BK=64, 3-stage cp.async) ----------------
#define BM 128
#define BN 128
#define BK 64
#define NSTAGE 3
#define A_STRIDE 144                       // 64 bf16 = 128B + 16B pad
#define B_STRIDE 272                       // 128 bf16 = 256B + 16B pad
#define OFF_AH 0
#define OFF_AL (128 * A_STRIDE)            // 18432
#define OFF_BH (2 * 128 * A_STRIDE)        // 36864
#define OFF_BL (OFF_BH + BK * B_STRIDE)    // 54272
#define STAGE_BYTES (OFF_BL + BK * B_STRIDE)   // 71680
#define GEMM_SMEM (NSTAGE * STAGE_BYTES)       // 215040

// ---------------- split-weight layout (elements), [K,N] row-major ----------
#define WSZ   (12ull * 1024 * 1024)
#define W1SZ  (12ull * 1024 * 4096)
#define WO_OFF   (3ull * WSZ)
#define W1_OFF   (WO_OFF + WSZ)
#define W2_OFF   (W1_OFF + W1SZ)
#define WLM_OFF  (W2_OFF + W1SZ)
#define WTOT     (WLM_OFF + 1024ull * 32000)

// ---------------- attention smem layout ----------------
#define QS 144
#define AT_QH 0
#define AT_QL 18432
#define AT_KH 36864
#define AT_KL 55296
#define AT_VH 73728
#define AT_VL 92160
#define ATTN_SMEM 110592

// ---------------- static device scratch ----------------
__device__ float g_x[BT * CC];
__device__ __nv_bfloat16 g_xnh [BT * CC],    g_xnl [BT * CC];
__device__ __nv_bfloat16 g_qkvh[BT * QKVLD], g_qkvl[BT * QKVLD];
__device__ __nv_bfloat16 g_yh  [BT * CC],    g_yl  [BT * CC];
__device__ __nv_bfloat16 g_hh  [BT * FF],    g_hl  [BT * FF];
__device__ __nv_bfloat16 g_whi[WTOT], g_wlo[WTOT];

// ---------------- helpers ----------------
__device__ __forceinline__ unsigned pack_bf16(float x, float y)
{
    __nv_bfloat162 h = __floats2bfloat162_rn(x, y);
    return *reinterpret_cast<unsigned*>(&h);
}
__device__ __forceinline__ void split_pair(float x, float y, unsigned& hi, unsigned& lo)
{
    float hx = __bfloat162float(__float2bfloat16(x));
    float hy = __bfloat162float(__float2bfloat16(y));
    hi = pack_bf16(x, y);
    lo = pack_bf16(x - hx, y - hy);
}
__device__ __forceinline__ void cp16(unsigned dst, const void* src)
{
    asm volatile("cp.async.cg.shared.global [%0],[%1],16;" :: "r"(dst), "l"(src));
}
__device__ __forceinline__ void ldsm4(unsigned* r, unsigned a)
{
    asm volatile("ldmatrix.sync.aligned.m8n8.x4.shared.b16 {%0,%1,%2,%3},[%4];"
                 : "=r"(r[0]), "=r"(r[1]), "=r"(r[2]), "=r"(r[3]) : "r"(a));
}
__device__ __forceinline__ void ldsm4t(unsigned* r, unsigned a)
{
    asm volatile("ldmatrix.sync.aligned.m8n8.x4.trans.shared.b16 {%0,%1,%2,%3},[%4];"
                 : "=r"(r[0]), "=r"(r[1]), "=r"(r[2]), "=r"(r[3]) : "r"(a));
}
__device__ __forceinline__ void mma_bf16(float* d, const unsigned* a, unsigned b0, unsigned b1)
{
    asm volatile("mma.sync.aligned.m16n8k16.row.col.f32.bf16.bf16.f32 "
                 "{%0,%1,%2,%3},{%4,%5,%6,%7},{%8,%9},{%0,%1,%2,%3};"
                 : "+f"(d[0]), "+f"(d[1]), "+f"(d[2]), "+f"(d[3])
                 : "r"(a[0]), "r"(a[1]), "r"(a[2]), "r"(a[3]),
                   "r"(b0), "r"(b1));
}

// ---------------- weight split kernels ----------------
__global__ void split_w_kernel(const float* __restrict__ src,
                               __nv_bfloat16* __restrict__ hi,
                               __nv_bfloat16* __restrict__ lo,
                               int n4)
{
    int i = blockIdx.x * 256 + threadIdx.x;
    if (i >= n4) return;
    float4 v = ((const float4*)src)[i];
    unsigned h0, l0, h1, l1;
    split_pair(v.x, v.y, h0, l0);
    split_pair(v.z, v.w, h1, l1);
    ((uint2*)hi)[i] = make_uint2(h0, h1);
    ((uint2*)lo)[i] = make_uint2(l0, l1);
}

__global__ void split_w3_kernel(const float* __restrict__ src,
                                __nv_bfloat16* __restrict__ hi,
                                __nv_bfloat16* __restrict__ lo,
                                int cofs)
{
    long i = (long)blockIdx.x * 256 + threadIdx.x;
    long e = i * 4;
    long l  = e >> 20;
    long rm = e & 1048575;
    long kk = rm >> 10;
    long n  = rm & 1023;
    float4 v = ((const float4*)src)[i];
    unsigned h0, l0, h1, l1;
    split_pair(v.x, v.y, h0, l0);
    split_pair(v.z, v.w, h1, l1);
    long d = l * 3145728 + kk * 3072 + cofs + n;
    *(uint2*)(hi + d) = make_uint2(h0, h1);
    *(uint2*)(lo + d) = make_uint2(l0, l1);
}

// ---------------- embedding ----------------
__global__ void embed_kernel(const int* __restrict__ idx,
                             const float* __restrict__ tok,
                             const float* __restrict__ pos,
                             float* __restrict__ x)
{
    int row = blockIdx.x;
    int t   = row & (TT - 1);
    int id  = idx[row];
    int c   = threadIdx.x * 4;
    float4 tv = *(const float4*)(tok + (size_t)id * CC + c);
    float4 pv = *(const float4*)(pos + (size_t)t  * CC + c);
    float4 o;
    o.x = tv.x + pv.x; o.y = tv.y + pv.y; o.z = tv.z + pv.z; o.w = tv.w + pv.w;
    *(float4*)(x + (size_t)row * CC + c) = o;
}

// ---------------- layernorm -> split bf16 hi/lo ----------------
__global__ void ln_kernel(const float* __restrict__ x,
                          __nv_bfloat16* __restrict__ oh,
                          __nv_bfloat16* __restrict__ ol,
                          const float* __restrict__ g, const float* __restrict__ b)
{
    int row = blockIdx.x;
    int tid = threadIdx.x;
    const float* xr = x + (size_t)row * CC;
    float4 xv = *(const float4*)(xr + tid * 4);
    float s  = xv.x + xv.y + xv.z + xv.w;
    float s2 = xv.x*xv.x + xv.y*xv.y + xv.z*xv.z + xv.w*xv.w;
    #pragma unroll
    for (int off = 16; off > 0; off >>= 1) {
        s  += __shfl_xor_sync(0xffffffffu, s,  off);
        s2 += __shfl_xor_sync(0xffffffffu, s2, off);
    }
    __shared__ float sh[16];
    int w = tid >> 5;
    if ((tid & 31) == 0) { sh[w] = s; sh[8 + w] = s2; }
    __syncthreads();
    s = 0.f; s2 = 0.f;
    #pragma unroll
    for (int i = 0; i < 8; i++) { s += sh[i]; s2 += sh[8 + i]; }
    float mean = s * (1.0f / CC);
    float var  = s2 * (1.0f / CC) - mean * mean;
    float rinv = rsqrtf(var + 1e-5f);
    float4 gv = *(const float4*)(g + tid * 4);
    float4 bv = *(const float4*)(b + tid * 4);
    float4 ov;
    ov.x = (xv.x - mean) * rinv * gv.x + bv.x;
    ov.y = (xv.y - mean) * rinv * gv.y + bv.y;
    ov.z = (xv.z - mean) * rinv * gv.z + bv.z;
    ov.w = (xv.w - mean) * rinv * gv.w + bv.w;
    unsigned h0, l0, h1, l1;
    split_pair(ov.x, ov.y, h0, l0);
    split_pair(ov.z, ov.w, h1, l1);
    size_t o = (size_t)row * CC + tid * 4;
    *(uint2*)(oh + o) = make_uint2(h0, h1);
    *(uint2*)(ol + o) = make_uint2(l0, l1);
}

// ---------------- tensor-core GEMM: pre-split bf16, BK=64, 3-stage cp.async -
// EPI: 0 fp32 out; 1 split out; 2 split out +bias,relu; 3 fp32 out +bias+resid
template <int EPI>
__global__ __launch_bounds__(256)
void bgemm_kernel(int M, int N, int K,
                  const __nv_bfloat16* __restrict__ Ah_,
                  const __nv_bfloat16* __restrict__ Al_,
                  const __nv_bfloat16* __restrict__ Bh_,
                  const __nv_bfloat16* __restrict__ Bl_,
                  float* __restrict__ outF,
                  __nv_bfloat16* __restrict__ outH,
                  __nv_bfloat16* __restrict__ outL,
                  const float* __restrict__ bias,
                  const float* __restrict__ resid)
{
    extern __shared__ char smem[];
    const unsigned sbase = (unsigned)__cvta_generic_to_shared(smem);
    const int tid  = threadIdx.x;
    const int bm   = blockIdx.y * BM;
    const int bn   = blockIdx.x * BN;
    const int warp = tid >> 5, lane = tid & 31;
    const int wm   = warp >> 2, wn = warp & 3;

    // producer: 16B chunks.  A: 128 rows x 8 chunks; B: 64 rows x 16 chunks.
    const int ar  = tid >> 3, ac = tid & 7;       // + i*32 rows
    const int br  = tid >> 4, bc = tid & 15;      // + i*16 rows

    auto prefetch = [&](int kt, int s) {
        const unsigned st = sbase + s * STAGE_BYTES;
        const int k0 = kt * BK;
        #pragma unroll
        for (int i = 0; i < 4; i++) {
            int r = ar + i * 32;
            unsigned off = (unsigned)(r * A_STRIDE + ac * 16);
            size_t g = (size_t)(bm + r) * K + k0 + ac * 8;
            cp16(st + OFF_AH + off, Ah_ + g);
            cp16(st + OFF_AL + off, Al_ + g);
        }
        #pragma unroll
        for (int i = 0; i < 4; i++) {
            int r = br + i * 16;
            unsigned off = (unsigned)(r * B_STRIDE + bc * 16);
            size_t g = (size_t)(k0 + r) * N + bn + bc * 8;
            cp16(st + OFF_BH + off, Bh_ + g);
            cp16(st + OFF_BL + off, Bl_ + g);
        }
    };

    const int kTiles = K / BK;
    prefetch(0, 0);
    asm volatile("cp.async.commit_group;");
    prefetch(1, 1);
    asm volatile("cp.async.commit_group;");

    float acc[4][4][4];
    #pragma unroll
    for (int i = 0; i < 4; i++)
        #pragma unroll
        for (int j = 0; j < 4; j++)
            #pragma unroll
            for (int r = 0; r < 4; r++) acc[i][j][r] = 0.f;

    const int am   = wm * 64 + (lane & 15);
    const int aKof = (lane >> 4) << 3;
    const int bk   = lane & 15;
    const int nb   = wn * 32 + ((lane >> 4) << 3);

    int stage = 0;
    for (int kt = 0; kt < kTiles; kt++) {
        asm volatile("cp.async.wait_group 1;");
        __syncthreads();                 // tile kt ready; buf (kt+2)%3 free
        if (kt + 2 < kTiles) prefetch(kt + 2, (kt + 2) % NSTAGE);
        asm volatile("cp.async.commit_group;");

        const unsigned st = sbase + stage * STAGE_BYTES;
        #pragma unroll
        for (int h = 0; h < 4; h++) {
            unsigned ah[4][4], al[4][4], bhf[2][4], blf[2][4];
            const int kc = h * 16 + aKof;
            #pragma unroll
            for (int i = 0; i < 4; i++) {
                unsigned arow_off = (unsigned)((am + i * 16) * A_STRIDE + kc * 2);
                ldsm4(ah[i], st + OFF_AH + arow_off);
                ldsm4(al[i], st + OFF_AL + arow_off);
            }
            const int bkh = h * 16 + bk;
            #pragma unroll
            for (int j = 0; j < 2; j++) {
                unsigned boff = (unsigned)(bkh * B_STRIDE + (nb + j * 16) * 2);
                ldsm4t(bhf[j], st + OFF_BH + boff);
                ldsm4t(blf[j], st + OFF_BL + boff);
            }
            #pragma unroll
            for (int i = 0; i < 4; i++) {
                #pragma unroll
                for (int jj = 0; jj < 4; jj++) {
                    const unsigned* ph = &bhf[jj >> 1][(jj & 1) * 2];
                    const unsigned* pl = &blf[jj >> 1][(jj & 1) * 2];
                    mma_bf16(acc[i][jj], ah[i], ph[0], ph[1]);
                    mma_bf16(acc[i][jj], al[i], ph[0], ph[1]);
                    mma_bf16(acc[i][jj], ah[i], pl[0], pl[1]);
                }
            }
        }
        stage = (stage + 1 == NSTAGE) ? 0 : stage + 1;
    }

    const int mrow = bm + wm * 64 + (lane >> 2);
    const int ncol = bn + wn * 32 + (lane & 3) * 2;
    #pragma unroll
    for (int i = 0; i < 4; i++) {
        #pragma unroll
        for (int jj = 0; jj < 4; jj++) {
            int r0 = mrow + i * 16;
            int c  = ncol + jj * 8;
            float2 v0 = make_float2(acc[i][jj][0], acc[i][jj][1]);
            float2 v1 = make_float2(acc[i][jj][2], acc[i][jj][3]);
            if (EPI == 2 || EPI == 3) {
                float b0v = bias[c], b1v = bias[c + 1];
                v0.x += b0v; v0.y += b1v; v1.x += b0v; v1.y += b1v;
            }
            if (EPI == 2) {
                v0.x = fmaxf(v0.x, 0.f); v0.y = fmaxf(v0.y, 0.f);
                v1.x = fmaxf(v1.x, 0.f); v1.y = fmaxf(v1.y, 0.f);
            }
            size_t o0 = (size_t)r0 * N + c;
            size_t o1 = (size_t)(r0 + 8) * N + c;
            if (EPI == 3) {
                float2 q0 = *(const float2*)(resid + o0);
                float2 q1 = *(const float2*)(resid + o1);
                v0.x += q0.x; v0.y += q0.y; v1.x += q1.x; v1.y += q1.y;
            }
            if (EPI == 0 || EPI == 3) {
                *(float2*)(outF + o0) = v0;
                *(float2*)(outF + o1) = v1;
            } else {
                unsigned h0, l0;
                split_pair(v0.x, v0.y, h0, l0);
                *(unsigned*)(outH + o0) = h0;
                *(unsigned*)(outL + o0) = l0;
                split_pair(v1.x, v1.y, h0, l0);
                *(unsigned*)(outH + o1) = h0;
                *(unsigned*)(outL + o1) = l0;
            }
        }
    }
}

// ---------------- fused flash attention (pre-split qkv in, split y out) ----
__global__ __launch_bounds__(256)
void attn_kernel(const __nv_bfloat16* __restrict__ qkvh,
                 const __nv_bfloat16* __restrict__ qkvl,
                 __nv_bfloat16* __restrict__ yh,
                 __nv_bfloat16* __restrict__ yl)
{
    extern __shared__ char sm[];
    const unsigned sb = (unsigned)__cvta_generic_to_shared(sm);
    const int qt   = blockIdx.x;
    const int bh   = blockIdx.y;
    const int b    = bh >> 4, h = bh & 15;
    const int tid  = threadIdx.x;
    const int warp = tid >> 5, lane = tid & 31;

    const int    qbase   = qt * 128;
    const size_t rowbase = (size_t)b * TT;
    const int    colh    = h * HD;

    for (int i = tid; i < 1024; i += 256) {
        int r = i >> 3, c8 = i & 7;
        size_t g = (rowbase + qbase + r) * QKVLD + colh + c8 * 8;
        *(uint4*)(sm + AT_QH + r * QS + c8 * 16) = *(const uint4*)(qkvh + g);
        *(uint4*)(sm + AT_QL + r * QS + c8 * 16) = *(const uint4*)(qkvl + g);
    }
    __syncthreads();

    unsigned qh[4][4], ql[4][4];
    {
        int rr = warp * 16 + (lane & 15);
        int kc = (lane >> 4) << 3;
        #pragma unroll
        for (int ks = 0; ks < 4; ks++) {
            unsigned off = (unsigned)(rr * QS + (ks * 16 + kc) * 2);
            ldsm4(qh[ks], sb + AT_QH + off);
            ldsm4(ql[ks], sb + AT_QL + off);
        }
    }

    float Oc[8][4];
    #pragma unroll
    for (int f = 0; f < 8; f++)
        #pragma unroll
        for (int r = 0; r < 4; r++) Oc[f][r] = 0.f;
    float m0 = -1e30f, m8 = -1e30f, l0s = 0.f, l8s = 0.f;

    for (int jt = 0; jt <= qt; jt++) {
        const int jbase = jt * 128;
        __syncthreads();
        for (int i = tid; i < 1024; i += 256) {
            int r = i >> 3, c8 = i & 7;
            size_t g = (rowbase + jbase + r) * QKVLD + colh + c8 * 8;
            *(uint4*)(sm + AT_KH + r * QS + c8 * 16) = *(const uint4*)(qkvh + g + 1024);
            *(uint4*)(sm + AT_KL + r * QS + c8 * 16) = *(const uint4*)(qkvl + g + 1024);
            *(uint4*)(sm + AT_VH + r * QS + c8 * 16) = *(const uint4*)(qkvh + g + 2048);
            *(uint4*)(sm + AT_VL + r * QS + c8 * 16) = *(const uint4*)(qkvl + g + 2048);
        }
        __syncthreads();

        float s[16][4];
        #pragma unroll
        for (int f = 0; f < 16; f++)
            #pragma unroll
            for (int r = 0; r < 4; r++) s[f][r] = 0.f;

        #pragma unroll
        for (int ks = 0; ks < 4; ks++) {
            #pragma unroll
            for (int ng = 0; ng < 8; ng++) {
                unsigned off = (unsigned)((ng * 16 + (lane & 15)) * QS +
                                          (ks * 16 + ((lane >> 4) << 3)) * 2);
                unsigned kh4[4], kl4[4];
                ldsm4(kh4, sb + AT_KH + off);
                ldsm4(kl4, sb + AT_KL + off);
                mma_bf16(s[2*ng],   qh[ks], kh4[0], kh4[2]);
                mma_bf16(s[2*ng],   ql[ks], kh4[0], kh4[2]);
                mma_bf16(s[2*ng],   qh[ks], kl4[0], kl4[2]);
                mma_bf16(s[2*ng+1], qh[ks], kh4[1], kh4[3]);
                mma_bf16(s[2*ng+1], ql[ks], kh4[1], kh4[3]);
                mma_bf16(s[2*ng+1], qh[ks], kl4[1], kl4[3]);
            }
        }

        #pragma unroll
        for (int f = 0; f < 16; f++) {
            s[f][0] *= 0.125f; s[f][1] *= 0.125f;
            s[f][2] *= 0.125f; s[f][3] *= 0.125f;
        }

        if (jt == qt) {
            int r0 = warp * 16 + (lane >> 2);
            #pragma unroll
            for (int f = 0; f < 16; f++) {
                int c = f * 8 + 2 * (lane & 3);
                if (c     > r0)     s[f][0] = -1e30f;
                if (c + 1 > r0)     s[f][1] = -1e30f;
                if (c     > r0 + 8) s[f][2] = -1e30f;
                if (c + 1 > r0 + 8) s[f][3] = -1e30f;
            }
        }

        float mx0 = -1e30f, mx8 = -1e30f;
        #pragma unroll
        for (int f = 0; f < 16; f++) {
            mx0 = fmaxf(mx0, fmaxf(s[f][0], s[f][1]));
            mx8 = fmaxf(mx8, fmaxf(s[f][2], s[f][3]));
        }
        mx0 = fmaxf(mx0, __shfl_xor_sync(0xffffffffu, mx0, 1));
        mx0 = fmaxf(mx0, __shfl_xor_sync(0xffffffffu, mx0, 2));
        mx8 = fmaxf(mx8, __shfl_xor_sync(0xffffffffu, mx8, 1));
        mx8 = fmaxf(mx8, __shfl_xor_sync(0xffffffffu, mx8, 2));
        float nm0 = fmaxf(m0, mx0), nm8 = fmaxf(m8, mx8);
        float a0 = __expf(m0 - nm0), a8 = __expf(m8 - nm8);

        float sum0 = 0.f, sum8 = 0.f;
        #pragma unroll
        for (int f = 0; f < 16; f++) {
            s[f][0] = __expf(s[f][0] - nm0);
            s[f][1] = __expf(s[f][1] - nm0);
            s[f][2] = __expf(s[f][2] - nm8);
            s[f][3] = __expf(s[f][3] - nm8);
            sum0 += s[f][0] + s[f][1];
            sum8 += s[f][2] + s[f][3];
        }
        sum0 += __shfl_xor_sync(0xffffffffu, sum0, 1);
        sum0 += __shfl_xor_sync(0xffffffffu, sum0, 2);
        sum8 += __shfl_xor_sync(0xffffffffu, sum8, 1);
        sum8 += __shfl_xor_sync(0xffffffffu, sum8, 2);
        l0s = l0s * a0 + sum0;
        l8s = l8s * a8 + sum8;
        m0 = nm0; m8 = nm8;
        #pragma unroll
        for (int f = 0; f < 8; f++) {
            Oc[f][0] *= a0; Oc[f][1] *= a0;
            Oc[f][2] *= a8; Oc[f][3] *= a8;
        }

        #pragma unroll
        for (int ks = 0; ks < 8; ks++) {
            unsigned ph4[4], pl4[4];
            split_pair(s[2*ks][0],   s[2*ks][1],   ph4[0], pl4[0]);
            split_pair(s[2*ks][2],   s[2*ks][3],   ph4[1], pl4[1]);
            split_pair(s[2*ks+1][0], s[2*ks+1][1], ph4[2], pl4[2]);
            split_pair(s[2*ks+1][2], s[2*ks+1][3], ph4[3], pl4[3]);
            #pragma unroll
            for (int ng = 0; ng < 4; ng++) {
                unsigned off = (unsigned)((ks * 16 + (lane & 15)) * QS +
                                          (ng * 16 + ((lane >> 4) << 3)) * 2);
                unsigned vh4[4], vl4[4];
                ldsm4t(vh4, sb + AT_VH + off);
                ldsm4t(vl4, sb + AT_VL + off);
                mma_bf16(Oc[2*ng],   ph4, vh4[0], vh4[1]);
                mma_bf16(Oc[2*ng],   pl4, vh4[0], vh4[1]);
                mma_bf16(Oc[2*ng],   ph4, vl4[0], vl4[1]);
                mma_bf16(Oc[2*ng+1], ph4, vh4[2], vh4[3]);
                mma_bf16(Oc[2*ng+1], pl4, vh4[2], vh4[3]);
                mma_bf16(Oc[2*ng+1], ph4, vl4[2], vl4[3]);
            }
        }
    }

    float i0 = 1.f / l0s, i8 = 1.f / l8s;
    int r0 = qbase + warp * 16 + (lane >> 2);
    #pragma unroll
    for (int f = 0; f < 8; f++) {
        int c = colh + f * 8 + 2 * (lane & 3);
        unsigned hh, ll;
        split_pair(Oc[f][0] * i0, Oc[f][1] * i0, hh, ll);
        *(unsigned*)(yh + (rowbase + r0) * CC + c) = hh;
        *(unsigned*)(yl + (rowbase + r0) * CC + c) = ll;
        split_pair(Oc[f][2] * i8, Oc[f][3] * i8, hh, ll);
        *(unsigned*)(yh + (rowbase + r0 + 8) * CC + c) = hh;
        *(unsigned*)(yl + (rowbase + r0 + 8) * CC + c) = ll;
    }
}

// ---------------- host launcher ----------------
template <typename T>
static T* sym_addr(const void* sym)
{
    void* p = nullptr;
    cudaGetSymbolAddress(&p, sym);
    return (T*)p;
}

extern "C" void kernel_launch(void* const* d_in, const int* in_sizes, int n_in,
                              void* d_out, int out_size)
{
    const int*   idx  = (const int*)  d_in[0];
    const float* tok  = (const float*)d_in[1];
    const float* pos  = (const float*)d_in[2];
    const float* wq   = (const float*)d_in[3];
    const float* wk   = (const float*)d_in[4];
    const float* wv   = (const float*)d_in[5];
    const float* wo   = (const float*)d_in[6];
    const float* bo   = (const float*)d_in[7];
    const float* ln1g = (const float*)d_in[8];
    const float* ln1b = (const float*)d_in[9];
    const float* ln2g = (const float*)d_in[10];
    const float* ln2b = (const float*)d_in[11];
    const float* w1   = (const float*)d_in[12];
    const float* b1   = (const float*)d_in[13];
    const float* w2   = (const float*)d_in[14];
    const float* b2   = (const float*)d_in[15];
    const float* lnfg = (const float*)d_in[16];
    const float* lnfb = (const float*)d_in[17];
    const float* wlm  = (const float*)d_in[18];
    float* out = (float*)d_out;

    float* x = sym_addr<float>(g_x);
    __nv_bfloat16* xnh  = sym_addr<__nv_bfloat16>(g_xnh);
    __nv_bfloat16* xnl  = sym_addr<__nv_bfloat16>(g_xnl);
    __nv_bfloat16* qkvh = sym_addr<__nv_bfloat16>(g_qkvh);
    __nv_bfloat16* qkvl = sym_addr<__nv_bfloat16>(g_qkvl);
    __nv_bfloat16* yh   = sym_addr<__nv_bfloat16>(g_yh);
    __nv_bfloat16* yl   = sym_addr<__nv_bfloat16>(g_yl);
    __nv_bfloat16* hh   = sym_addr<__nv_bfloat16>(g_hh);
    __nv_bfloat16* hl   = sym_addr<__nv_bfloat16>(g_hl);
    __nv_bfloat16* whi  = sym_addr<__nv_bfloat16>(g_whi);
    __nv_bfloat16* wlo  = sym_addr<__nv_bfloat16>(g_wlo);

    cudaFuncSetAttribute((const void*)bgemm_kernel<0>,
                         cudaFuncAttributeMaxDynamicSharedMemorySize, GEMM_SMEM);
    cudaFuncSetAttribute((const void*)bgemm_kernel<1>,
                         cudaFuncAttributeMaxDynamicSharedMemorySize, GEMM_SMEM);
    cudaFuncSetAttribute((const void*)bgemm_kernel<2>,
                         cudaFuncAttributeMaxDynamicSharedMemorySize, GEMM_SMEM);
    cudaFuncSetAttribute((const void*)bgemm_kernel<3>,
                         cudaFuncAttributeMaxDynamicSharedMemorySize, GEMM_SMEM);
    cudaFuncSetAttribute((const void*)attn_kernel,
                         cudaFuncAttributeMaxDynamicSharedMemorySize, ATTN_SMEM);

    split_w3_kernel<<<12288, 256>>>(wq, whi, wlo, 0);
    split_w3_kernel<<<12288, 256>>>(wk, whi, wlo, 1024);
    split_w3_kernel<<<12288, 256>>>(wv, whi, wlo, 2048);
    split_w_kernel<<<12288, 256>>>(wo,  whi + WO_OFF,  wlo + WO_OFF,  (int)(WSZ / 4));
    split_w_kernel<<<49152, 256>>>(w1,  whi + W1_OFF,  wlo + W1_OFF,  (int)(W1SZ / 4));
    split_w_kernel<<<49152, 256>>>(w2,  whi + W2_OFF,  wlo + W2_OFF,  (int)(W1SZ / 4));
    split_w_kernel<<<32000, 256>>>(wlm, whi + WLM_OFF, wlo + WLM_OFF, 8192000);

    embed_kernel<<<BT, 256>>>(idx, tok, pos, x);

    const dim3 gQkv (QKVLD / BN, BT / BM);  // (24,16)
    const dim3 gProj(CC / BN, BT / BM);     // (8,16)
    const dim3 gMlp1(FF / BN, BT / BM);     // (32,16)
    const dim3 gLm  (VV / BN, BT / BM);     // (250,16)
    const dim3 gAtt (4, BH);

    for (int l = 0; l < NL; l++) {
        size_t o3 = (size_t)l * 3145728;
        size_t oo = WO_OFF + (size_t)l * 1048576;
        size_t o1 = W1_OFF + (size_t)l * 4194304;
        size_t o2 = W2_OFF + (size_t)l * 4194304;

        ln_kernel<<<BT, 256>>>(x, xnh, xnl, ln1g + l * CC, ln1b + l * CC);
        bgemm_kernel<1><<<gQkv, 256, GEMM_SMEM>>>(BT, QKVLD, CC, xnh, xnl,
                                                  whi + o3, wlo + o3,
                                                  nullptr, qkvh, qkvl, nullptr, nullptr);
        attn_kernel<<<gAtt, 256, ATTN_SMEM>>>(qkvh, qkvl, yh, yl);
        bgemm_kernel<3><<<gProj, 256, GEMM_SMEM>>>(BT, CC, CC, yh, yl,
                                                   whi + oo, wlo + oo,
                                                   x, nullptr, nullptr, bo + l * CC, x);
        ln_kernel<<<BT, 256>>>(x, xnh, xnl, ln2g + l * CC, ln2b + l * CC);
        bgemm_kernel<2><<<gMlp1, 256, GEMM_SMEM>>>(BT, FF, CC, xnh, xnl,
                                                   whi + o1, wlo + o1,
                                                   nullptr, hh, hl, b1 + l * FF, nullptr);
        bgemm_kernel<3><<<gProj, 256, GEMM_SMEM>>>(BT, CC, FF, hh, hl,
                                                   whi + o2, wlo + o2,
                                                   x, nullptr, nullptr, b2 + l * CC, x);
    }

    ln_kernel<<<BT, 256>>>(x, xnh, xnl, lnfg, lnfb);
    bgemm_kernel<0><<<gLm, 256, GEMM_SMEM>>>(BT, VV, CC, xnh, xnl,
                                             whi + WLM_OFF, wlo + WLM_OFF,
                                             out, nullptr, nullptr, nullptr, nullptr);
}

// round 16
// speedup vs baseline: 1.0860x; 1.0213x over previous
#include <cuda_runtime.h>
#include <cuda_bf16.h>

// ---------------- problem constants ----------------
#define NL   12
#define CC   1024
#define TT   512
#define NH   16
#define HD   64
#define FF   4096
#define BT   2048            // B*T
#define VV   32000
#define BH   64              // B*NH
#define QKVLD 3072           // fused qkv leading dim

// ---------------- GEMM tile config (BK=64, 3-stage cp.async) ----------------
#define BM 128
#define BN 128
#define BK 64
#define NSTAGE 3
#define A_STRIDE 144                       // 64 bf16 = 128B + 16B pad
#define B_STRIDE 272                       // 128 bf16 = 256B + 16B pad
#define OFF_AH 0
#define OFF_AL (128 * A_STRIDE)            // 18432
#define OFF_BH (2 * 128 * A_STRIDE)        // 36864
#define OFF_BL (OFF_BH + BK * B_STRIDE)    // 54272
#define STAGE_BYTES (OFF_BL + BK * B_STRIDE)   // 71680
#define GEMM_SMEM (NSTAGE * STAGE_BYTES)       // 215040

// ---------------- split-weight layout (elements), [K,N] row-major ----------
#define WSZ   (12ull * 1024 * 1024)
#define W1SZ  (12ull * 1024 * 4096)
#define WO_OFF   (3ull * WSZ)
#define W1_OFF   (WO_OFF + WSZ)
#define W2_OFF   (W1_OFF + W1SZ)
#define WLM_OFF  (W2_OFF + W1SZ)
#define WTOT     (WLM_OFF + 1024ull * 32000)

// ---------------- attention smem layout ----------------
#define QS 144
#define AT_QH 0
#define AT_QL 18432
#define AT_KH 36864
#define AT_KL 55296
#define AT_VH 73728
#define AT_VL 92160
#define ATTN_SMEM 110592

// ---------------- static device scratch ----------------
__device__ float g_x[BT * CC];
__device__ __nv_bfloat16 g_xnh [BT * CC],    g_xnl [BT * CC];
__device__ __nv_bfloat16 g_qkvh[BT * QKVLD], g_qkvl[BT * QKVLD];
__device__ __nv_bfloat16 g_yh  [BT * CC],    g_yl  [BT * CC];
__device__ __nv_bfloat16 g_hh  [BT * FF],    g_hl  [BT * FF];
__device__ __nv_bfloat16 g_whi[WTOT], g_wlo[WTOT];

// ---------------- helpers ----------------
__device__ __forceinline__ unsigned pack_bf16(float x, float y)
{
    __nv_bfloat162 h = __floats2bfloat162_rn(x, y);
    return *reinterpret_cast<unsigned*>(&h);
}
__device__ __forceinline__ void split_pair(float x, float y, unsigned& hi, unsigned& lo)
{
    float hx = __bfloat162float(__float2bfloat16(x));
    float hy = __bfloat162float(__float2bfloat16(y));
    hi = pack_bf16(x, y);
    lo = pack_bf16(x - hx, y - hy);
}
__device__ __forceinline__ void cp16(unsigned dst, const void* src)
{
    asm volatile("cp.async.cg.shared.global [%0],[%1],16;" :: "r"(dst), "l"(src));
}
__device__ __forceinline__ void ldsm4(unsigned* r, unsigned a)
{
    asm volatile("ldmatrix.sync.aligned.m8n8.x4.shared.b16 {%0,%1,%2,%3},[%4];"
                 : "=r"(r[0]), "=r"(r[1]), "=r"(r[2]), "=r"(r[3]) : "r"(a));
}
__device__ __forceinline__ void ldsm4t(unsigned* r, unsigned a)
{
    asm volatile("ldmatrix.sync.aligned.m8n8.x4.trans.shared.b16 {%0,%1,%2,%3},[%4];"
                 : "=r"(r[0]), "=r"(r[1]), "=r"(r[2]), "=r"(r[3]) : "r"(a));
}
__device__ __forceinline__ void mma_bf16(float* d, const unsigned* a, unsigned b0, unsigned b1)
{
    asm volatile("mma.sync.aligned.m16n8k16.row.col.f32.bf16.bf16.f32 "
                 "{%0,%1,%2,%3},{%4,%5,%6,%7},{%8,%9},{%0,%1,%2,%3};"
                 : "+f"(d[0]), "+f"(d[1]), "+f"(d[2]), "+f"(d[3])
                 : "r"(a[0]), "r"(a[1]), "r"(a[2]), "r"(a[3]),
                   "r"(b0), "r"(b1));
}

// ---------------- weight split kernels ----------------
__global__ void split_w_kernel(const float* __restrict__ src,
                               __nv_bfloat16* __restrict__ hi,
                               __nv_bfloat16* __restrict__ lo,
                               int n4)
{
    int i = blockIdx.x * 256 + threadIdx.x;
    if (i >= n4) return;
    float4 v = ((const float4*)src)[i];
    unsigned h0, l0, h1, l1;
    split_pair(v.x, v.y, h0, l0);
    split_pair(v.z, v.w, h1, l1);
    ((uint2*)hi)[i] = make_uint2(h0, h1);
    ((uint2*)lo)[i] = make_uint2(l0, l1);
}

__global__ void split_w3_kernel(const float* __restrict__ src,
                                __nv_bfloat16* __restrict__ hi,
                                __nv_bfloat16* __restrict__ lo,
                                int cofs)
{
    long i = (long)blockIdx.x * 256 + threadIdx.x;
    long e = i * 4;
    long l  = e >> 20;
    long rm = e & 1048575;
    long kk = rm >> 10;
    long n  = rm & 1023;
    float4 v = ((const float4*)src)[i];
    unsigned h0, l0, h1, l1;
    split_pair(v.x, v.y, h0, l0);
    split_pair(v.z, v.w, h1, l1);
    long d = l * 3145728 + kk * 3072 + cofs + n;
    *(uint2*)(hi + d) = make_uint2(h0, h1);
    *(uint2*)(lo + d) = make_uint2(l0, l1);
}

// ---------------- embedding ----------------
__global__ void embed_kernel(const int* __restrict__ idx,
                             const float* __restrict__ tok,
                             const float* __restrict__ pos,
                             float* __restrict__ x)
{
    int row = blockIdx.x;
    int t   = row & (TT - 1);
    int id  = idx[row];
    int c   = threadIdx.x * 4;
    float4 tv = *(const float4*)(tok + (size_t)id * CC + c);
    float4 pv = *(const float4*)(pos + (size_t)t  * CC + c);
    float4 o;
    o.x = tv.x + pv.x; o.y = tv.y + pv.y; o.z = tv.z + pv.z; o.w = tv.w + pv.w;
    *(float4*)(x + (size_t)row * CC + c) = o;
}

// ---------------- layernorm -> split bf16 hi/lo ----------------
__global__ void ln_kernel(const float* __restrict__ x,
                          __nv_bfloat16* __restrict__ oh,
                          __nv_bfloat16* __restrict__ ol,
                          const float* __restrict__ g, const float* __restrict__ b)
{
    int row = blockIdx.x;
    int tid = threadIdx.x;
    const float* xr = x + (size_t)row * CC;
    float4 xv = *(const float4*)(xr + tid * 4);
    float s  = xv.x + xv.y + xv.z + xv.w;
    float s2 = xv.x*xv.x + xv.y*xv.y + xv.z*xv.z + xv.w*xv.w;
    #pragma unroll
    for (int off = 16; off > 0; off >>= 1) {
        s  += __shfl_xor_sync(0xffffffffu, s,  off);
        s2 += __shfl_xor_sync(0xffffffffu, s2, off);
    }
    __shared__ float sh[16];
    int w = tid >> 5;
    if ((tid & 31) == 0) { sh[w] = s; sh[8 + w] = s2; }
    __syncthreads();
    s = 0.f; s2 = 0.f;
    #pragma unroll
    for (int i = 0; i < 8; i++) { s += sh[i]; s2 += sh[8 + i]; }
    float mean = s * (1.0f / CC);
    float var  = s2 * (1.0f / CC) - mean * mean;
    float rinv = rsqrtf(var + 1e-5f);
    float4 gv = *(const float4*)(g + tid * 4);
    float4 bv = *(const float4*)(b + tid * 4);
    float4 ov;
    ov.x = (xv.x - mean) * rinv * gv.x + bv.x;
    ov.y = (xv.y - mean) * rinv * gv.y + bv.y;
    ov.z = (xv.z - mean) * rinv * gv.z + bv.z;
    ov.w = (xv.w - mean) * rinv * gv.w + bv.w;
    unsigned h0, l0, h1, l1;
    split_pair(ov.x, ov.y, h0, l0);
    split_pair(ov.z, ov.w, h1, l1);
    size_t o = (size_t)row * CC + tid * 4;
    *(uint2*)(oh + o) = make_uint2(h0, h1);
    *(uint2*)(ol + o) = make_uint2(l0, l1);
}

// ---------------- tensor-core GEMM: pre-split bf16, BK=64, 3-stage cp.async -
// Pass-major mma ordering: 16 independent mma between accumulator reuses.
// EPI: 0 fp32 out; 1 split out; 2 split out +bias,relu; 3 fp32 out +bias+resid
template <int EPI>
__global__ __launch_bounds__(256)
void bgemm_kernel(int M, int N, int K,
                  const __nv_bfloat16* __restrict__ Ah_,
                  const __nv_bfloat16* __restrict__ Al_,
                  const __nv_bfloat16* __restrict__ Bh_,
                  const __nv_bfloat16* __restrict__ Bl_,
                  float* __restrict__ outF,
                  __nv_bfloat16* __restrict__ outH,
                  __nv_bfloat16* __restrict__ outL,
                  const float* __restrict__ bias,
                  const float* __restrict__ resid)
{
    extern __shared__ char smem[];
    const unsigned sbase = (unsigned)__cvta_generic_to_shared(smem);
    const int tid  = threadIdx.x;
    const int bm   = blockIdx.y * BM;
    const int bn   = blockIdx.x * BN;
    const int warp = tid >> 5, lane = tid & 31;
    const int wm   = warp >> 2, wn = warp & 3;

    // producer: 16B chunks.  A: 128 rows x 8 chunks; B: 64 rows x 16 chunks.
    const int ar  = tid >> 3, ac = tid & 7;       // + i*32 rows
    const int br  = tid >> 4, bc = tid & 15;      // + i*16 rows

    auto prefetch = [&](int kt, int s) {
        const unsigned st = sbase + s * STAGE_BYTES;
        const int k0 = kt * BK;
        #pragma unroll
        for (int i = 0; i < 4; i++) {
            int r = ar + i * 32;
            unsigned off = (unsigned)(r * A_STRIDE + ac * 16);
            size_t g = (size_t)(bm + r) * K + k0 + ac * 8;
            cp16(st + OFF_AH + off, Ah_ + g);
            cp16(st + OFF_AL + off, Al_ + g);
        }
        #pragma unroll
        for (int i = 0; i < 4; i++) {
            int r = br + i * 16;
            unsigned off = (unsigned)(r * B_STRIDE + bc * 16);
            size_t g = (size_t)(k0 + r) * N + bn + bc * 8;
            cp16(st + OFF_BH + off, Bh_ + g);
            cp16(st + OFF_BL + off, Bl_ + g);
        }
    };

    const int kTiles = K / BK;
    prefetch(0, 0);
    asm volatile("cp.async.commit_group;");
    prefetch(1, 1);
    asm volatile("cp.async.commit_group;");

    float acc[4][4][4];
    #pragma unroll
    for (int i = 0; i < 4; i++)
        #pragma unroll
        for (int j = 0; j < 4; j++)
            #pragma unroll
            for (int r = 0; r < 4; r++) acc[i][j][r] = 0.f;

    const int am   = wm * 64 + (lane & 15);
    const int aKof = (lane >> 4) << 3;
    const int bk   = lane & 15;
    const int nb   = wn * 32 + ((lane >> 4) << 3);

    int stage = 0;
    for (int kt = 0; kt < kTiles; kt++) {
        asm volatile("cp.async.wait_group 1;");
        __syncthreads();                 // tile kt ready; buf (kt+2)%3 free
        if (kt + 2 < kTiles) prefetch(kt + 2, (kt + 2) % NSTAGE);
        asm volatile("cp.async.commit_group;");

        const unsigned st = sbase + stage * STAGE_BYTES;
        #pragma unroll
        for (int h = 0; h < 4; h++) {
            unsigned ah[4][4], al[4][4], bhf[2][4], blf[2][4];
            const int kc = h * 16 + aKof;
            #pragma unroll
            for (int i = 0; i < 4; i++) {
                unsigned arow_off = (unsigned)((am + i * 16) * A_STRIDE + kc * 2);
                ldsm4(ah[i], st + OFF_AH + arow_off);
                ldsm4(al[i], st + OFF_AL + arow_off);
            }
            const int bkh = h * 16 + bk;
            #pragma unroll
            for (int j = 0; j < 2; j++) {
                unsigned boff = (unsigned)(bkh * B_STRIDE + (nb + j * 16) * 2);
                ldsm4t(bhf[j], st + OFF_BH + boff);
                ldsm4t(blf[j], st + OFF_BL + boff);
            }
            // ---- pass-major: 16 independent mma per pass ----
            #pragma unroll
            for (int i = 0; i < 4; i++) {
                #pragma unroll
                for (int jj = 0; jj < 4; jj++) {
                    const unsigned* ph = &bhf[jj >> 1][(jj & 1) * 2];
                    mma_bf16(acc[i][jj], ah[i], ph[0], ph[1]);
                }
            }
            #pragma unroll
            for (int i = 0; i < 4; i++) {
                #pragma unroll
                for (int jj = 0; jj < 4; jj++) {
                    const unsigned* ph = &bhf[jj >> 1][(jj & 1) * 2];
                    mma_bf16(acc[i][jj], al[i], ph[0], ph[1]);
                }
            }
            #pragma unroll
            for (int i = 0; i < 4; i++) {
                #pragma unroll
                for (int jj = 0; jj < 4; jj++) {
                    const unsigned* pl = &blf[jj >> 1][(jj & 1) * 2];
                    mma_bf16(acc[i][jj], ah[i], pl[0], pl[1]);
                }
            }
        }
        stage = (stage + 1 == NSTAGE) ? 0 : stage + 1;
    }

    const int mrow = bm + wm * 64 + (lane >> 2);
    const int ncol = bn + wn * 32 + (lane & 3) * 2;
    #pragma unroll
    for (int i = 0; i < 4; i++) {
        #pragma unroll
        for (int jj = 0; jj < 4; jj++) {
            int r0 = mrow + i * 16;
            int c  = ncol + jj * 8;
            float2 v0 = make_float2(acc[i][jj][0], acc[i][jj][1]);
            float2 v1 = make_float2(acc[i][jj][2], acc[i][jj][3]);
            if (EPI == 2 || EPI == 3) {
                float b0v = bias[c], b1v = bias[c + 1];
                v0.x += b0v; v0.y += b1v; v1.x += b0v; v1.y += b1v;
            }
            if (EPI == 2) {
                v0.x = fmaxf(v0.x, 0.f); v0.y = fmaxf(v0.y, 0.f);
                v1.x = fmaxf(v1.x, 0.f); v1.y = fmaxf(v1.y, 0.f);
            }
            size_t o0 = (size_t)r0 * N + c;
            size_t o1 = (size_t)(r0 + 8) * N + c;
            if (EPI == 3) {
                float2 q0 = *(const float2*)(resid + o0);
                float2 q1 = *(const float2*)(resid + o1);
                v0.x += q0.x; v0.y += q0.y; v1.x += q1.x; v1.y += q1.y;
            }
            if (EPI == 0 || EPI == 3) {
                *(float2*)(outF + o0) = v0;
                *(float2*)(outF + o1) = v1;
            } else {
                unsigned h0, l0;
                split_pair(v0.x, v0.y, h0, l0);
                *(unsigned*)(outH + o0) = h0;
                *(unsigned*)(outL + o0) = l0;
                split_pair(v1.x, v1.y, h0, l0);
                *(unsigned*)(outH + o1) = h0;
                *(unsigned*)(outL + o1) = l0;
            }
        }
    }
}

// ---------------- fused flash attention (pre-split qkv in, split y out) ----
__global__ __launch_bounds__(256)
void attn_kernel(const __nv_bfloat16* __restrict__ qkvh,
                 const __nv_bfloat16* __restrict__ qkvl,
                 __nv_bfloat16* __restrict__ yh,
                 __nv_bfloat16* __restrict__ yl)
{
    extern __shared__ char sm[];
    const unsigned sb = (unsigned)__cvta_generic_to_shared(sm);
    const int qt   = blockIdx.x;
    const int bh   = blockIdx.y;
    const int b    = bh >> 4, h = bh & 15;
    const int tid  = threadIdx.x;
    const int warp = tid >> 5, lane = tid & 31;

    const int    qbase   = qt * 128;
    const size_t rowbase = (size_t)b * TT;
    const int    colh    = h * HD;

    for (int i = tid; i < 1024; i += 256) {
        int r = i >> 3, c8 = i & 7;
        size_t g = (rowbase + qbase + r) * QKVLD + colh + c8 * 8;
        *(uint4*)(sm + AT_QH + r * QS + c8 * 16) = *(const uint4*)(qkvh + g);
        *(uint4*)(sm + AT_QL + r * QS + c8 * 16) = *(const uint4*)(qkvl + g);
    }
    __syncthreads();

    unsigned qh[4][4], ql[4][4];
    {
        int rr = warp * 16 + (lane & 15);
        int kc = (lane >> 4) << 3;
        #pragma unroll
        for (int ks = 0; ks < 4; ks++) {
            unsigned off = (unsigned)(rr * QS + (ks * 16 + kc) * 2);
            ldsm4(qh[ks], sb + AT_QH + off);
            ldsm4(ql[ks], sb + AT_QL + off);
        }
    }

    float Oc[8][4];
    #pragma unroll
    for (int f = 0; f < 8; f++)
        #pragma unroll
        for (int r = 0; r < 4; r++) Oc[f][r] = 0.f;
    float m0 = -1e30f, m8 = -1e30f, l0s = 0.f, l8s = 0.f;

    for (int jt = 0; jt <= qt; jt++) {
        const int jbase = jt * 128;
        __syncthreads();
        for (int i = tid; i < 1024; i += 256) {
            int r = i >> 3, c8 = i & 7;
            size_t g = (rowbase + jbase + r) * QKVLD + colh + c8 * 8;
            *(uint4*)(sm + AT_KH + r * QS + c8 * 16) = *(const uint4*)(qkvh + g + 1024);
            *(uint4*)(sm + AT_KL + r * QS + c8 * 16) = *(const uint4*)(qkvl + g + 1024);
            *(uint4*)(sm + AT_VH + r * QS + c8 * 16) = *(const uint4*)(qkvh + g + 2048);
            *(uint4*)(sm + AT_VL + r * QS + c8 * 16) = *(const uint4*)(qkvl + g + 2048);
        }
        __syncthreads();

        float s[16][4];
        #pragma unroll
        for (int f = 0; f < 16; f++)
            #pragma unroll
            for (int r = 0; r < 4; r++) s[f][r] = 0.f;

        #pragma unroll
        for (int ks = 0; ks < 4; ks++) {
            #pragma unroll
            for (int ng = 0; ng < 8; ng++) {
                unsigned off = (unsigned)((ng * 16 + (lane & 15)) * QS +
                                          (ks * 16 + ((lane >> 4) << 3)) * 2);
                unsigned kh4[4], kl4[4];
                ldsm4(kh4, sb + AT_KH + off);
                ldsm4(kl4, sb + AT_KL + off);
                // interleaved: accumulator chains spaced by 2
                mma_bf16(s[2*ng],   qh[ks], kh4[0], kh4[2]);
                mma_bf16(s[2*ng+1], qh[ks], kh4[1], kh4[3]);
                mma_bf16(s[2*ng],   ql[ks], kh4[0], kh4[2]);
                mma_bf16(s[2*ng+1], ql[ks], kh4[1], kh4[3]);
                mma_bf16(s[2*ng],   qh[ks], kl4[0], kl4[2]);
                mma_bf16(s[2*ng+1], qh[ks], kl4[1], kl4[3]);
            }
        }

        #pragma unroll
        for (int f = 0; f < 16; f++) {
            s[f][0] *= 0.125f; s[f][1] *= 0.125f;
            s[f][2] *= 0.125f; s[f][3] *= 0.125f;
        }

        if (jt == qt) {
            int r0 = warp * 16 + (lane >> 2);
            #pragma unroll
            for (int f = 0; f < 16; f++) {
                int c = f * 8 + 2 * (lane & 3);
                if (c     > r0)     s[f][0] = -1e30f;
                if (c + 1 > r0)     s[f][1] = -1e30f;
                if (c     > r0 + 8) s[f][2] = -1e30f;
                if (c + 1 > r0 + 8) s[f][3] = -1e30f;
            }
        }

        float mx0 = -1e30f, mx8 = -1e30f;
        #pragma unroll
        for (int f = 0; f < 16; f++) {
            mx0 = fmaxf(mx0, fmaxf(s[f][0], s[f][1]));
            mx8 = fmaxf(mx8, fmaxf(s[f][2], s[f][3]));
        }
        mx0 = fmaxf(mx0, __shfl_xor_sync(0xffffffffu, mx0, 1));
        mx0 = fmaxf(mx0, __shfl_xor_sync(0xffffffffu, mx0, 2));
        mx8 = fmaxf(mx8, __shfl_xor_sync(0xffffffffu, mx8, 1));
        mx8 = fmaxf(mx8, __shfl_xor_sync(0xffffffffu, mx8, 2));
        float nm0 = fmaxf(m0, mx0), nm8 = fmaxf(m8, mx8);
        float a0 = __expf(m0 - nm0), a8 = __expf(m8 - nm8);

        float sum0 = 0.f, sum8 = 0.f;
        #pragma unroll
        for (int f = 0; f < 16; f++) {
            s[f][0] = __expf(s[f][0] - nm0);
            s[f][1] = __expf(s[f][1] - nm0);
            s[f][2] = __expf(s[f][2] - nm8);
            s[f][3] = __expf(s[f][3] - nm8);
            sum0 += s[f][0] + s[f][1];
            sum8 += s[f][2] + s[f][3];
        }
        sum0 += __shfl_xor_sync(0xffffffffu, sum0, 1);
        sum0 += __shfl_xor_sync(0xffffffffu, sum0, 2);
        sum8 += __shfl_xor_sync(0xffffffffu, sum8, 1);
        sum8 += __shfl_xor_sync(0xffffffffu, sum8, 2);
        l0s = l0s * a0 + sum0;
        l8s = l8s * a8 + sum8;
        m0 = nm0; m8 = nm8;
        #pragma unroll
        for (int f = 0; f < 8; f++) {
            Oc[f][0] *= a0; Oc[f][1] *= a0;
            Oc[f][2] *= a8; Oc[f][3] *= a8;
        }

        #pragma unroll
        for (int ks = 0; ks < 8; ks++) {
            unsigned ph4[4], pl4[4];
            split_pair(s[2*ks][0],   s[2*ks][1],   ph4[0], pl4[0]);
            split_pair(s[2*ks][2],   s[2*ks][3],   ph4[1], pl4[1]);
            split_pair(s[2*ks+1][0], s[2*ks+1][1], ph4[2], pl4[2]);
            split_pair(s[2*ks+1][2], s[2*ks+1][3], ph4[3], pl4[3]);
            #pragma unroll
            for (int ng = 0; ng < 4; ng++) {
                unsigned off = (unsigned)((ks * 16 + (lane & 15)) * QS +
                                          (ng * 16 + ((lane >> 4) << 3)) * 2);
                unsigned vh4[4], vl4[4];
                ldsm4t(vh4, sb + AT_VH + off);
                ldsm4t(vl4, sb + AT_VL + off);
                // interleaved: accumulator chains spaced by 2
                mma_bf16(Oc[2*ng],   ph4, vh4[0], vh4[1]);
                mma_bf16(Oc[2*ng+1], ph4, vh4[2], vh4[3]);
                mma_bf16(Oc[2*ng],   pl4, vh4[0], vh4[1]);
                mma_bf16(Oc[2*ng+1], pl4, vh4[2], vh4[3]);
                mma_bf16(Oc[2*ng],   ph4, vl4[0], vl4[1]);
                mma_bf16(Oc[2*ng+1], ph4, vl4[2], vl4[3]);
            }
        }
    }

    float i0 = 1.f / l0s, i8 = 1.f / l8s;
    int r0 = qbase + warp * 16 + (lane >> 2);
    #pragma unroll
    for (int f = 0; f < 8; f++) {
        int c = colh + f * 8 + 2 * (lane & 3);
        unsigned hh, ll;
        split_pair(Oc[f][0] * i0, Oc[f][1] * i0, hh, ll);
        *(unsigned*)(yh + (rowbase + r0) * CC + c) = hh;
        *(unsigned*)(yl + (rowbase + r0) * CC + c) = ll;
        split_pair(Oc[f][2] * i8, Oc[f][3] * i8, hh, ll);
        *(unsigned*)(yh + (rowbase + r0 + 8) * CC + c) = hh;
        *(unsigned*)(yl + (rowbase + r0 + 8) * CC + c) = ll;
    }
}

// ---------------- host launcher ----------------
template <typename T>
static T* sym_addr(const void* sym)
{
    void* p = nullptr;
    cudaGetSymbolAddress(&p, sym);
    return (T*)p;
}

extern "C" void kernel_launch(void* const* d_in, const int* in_sizes, int n_in,
                              void* d_out, int out_size)
{
    const int*   idx  = (const int*)  d_in[0];
    const float* tok  = (const float*)d_in[1];
    const float* pos  = (const float*)d_in[2];
    const float* wq   = (const float*)d_in[3];
    const float* wk   = (const float*)d_in[4];
    const float* wv   = (const float*)d_in[5];
    const float* wo   = (const float*)d_in[6];
    const float* bo   = (const float*)d_in[7];
    const float* ln1g = (const float*)d_in[8];
    const float* ln1b = (const float*)d_in[9];
    const float* ln2g = (const float*)d_in[10];
    const float* ln2b = (const float*)d_in[11];
    const float* w1   = (const float*)d_in[12];
    const float* b1   = (const float*)d_in[13];
    const float* w2   = (const float*)d_in[14];
    const float* b2   = (const float*)d_in[15];
    const float* lnfg = (const float*)d_in[16];
    const float* lnfb = (const float*)d_in[17];
    const float* wlm  = (const float*)d_in[18];
    float* out = (float*)d_out;

    float* x = sym_addr<float>(g_x);
    __nv_bfloat16* xnh  = sym_addr<__nv_bfloat16>(g_xnh);
    __nv_bfloat16* xnl  = sym_addr<__nv_bfloat16>(g_xnl);
    __nv_bfloat16* qkvh = sym_addr<__nv_bfloat16>(g_qkvh);
    __nv_bfloat16* qkvl = sym_addr<__nv_bfloat16>(g_qkvl);
    __nv_bfloat16* yh   = sym_addr<__nv_bfloat16>(g_yh);
    __nv_bfloat16* yl   = sym_addr<__nv_bfloat16>(g_yl);
    __nv_bfloat16* hh   = sym_addr<__nv_bfloat16>(g_hh);
    __nv_bfloat16* hl   = sym_addr<__nv_bfloat16>(g_hl);
    __nv_bfloat16* whi  = sym_addr<__nv_bfloat16>(g_whi);
    __nv_bfloat16* wlo  = sym_addr<__nv_bfloat16>(g_wlo);

    cudaFuncSetAttribute((const void*)bgemm_kernel<0>,
                         cudaFuncAttributeMaxDynamicSharedMemorySize, GEMM_SMEM);
    cudaFuncSetAttribute((const void*)bgemm_kernel<1>,
                         cudaFuncAttributeMaxDynamicSharedMemorySize, GEMM_SMEM);
    cudaFuncSetAttribute((const void*)bgemm_kernel<2>,
                         cudaFuncAttributeMaxDynamicSharedMemorySize, GEMM_SMEM);
    cudaFuncSetAttribute((const void*)bgemm_kernel<3>,
                         cudaFuncAttributeMaxDynamicSharedMemorySize, GEMM_SMEM);
    cudaFuncSetAttribute((const void*)attn_kernel,
                         cudaFuncAttributeMaxDynamicSharedMemorySize, ATTN_SMEM);

    split_w3_kernel<<<12288, 256>>>(wq, whi, wlo, 0);
    split_w3_kernel<<<12288, 256>>>(wk, whi, wlo, 1024);
    split_w3_kernel<<<12288, 256>>>(wv, whi, wlo, 2048);
    split_w_kernel<<<12288, 256>>>(wo,  whi + WO_OFF,  wlo + WO_OFF,  (int)(WSZ / 4));
    split_w_kernel<<<49152, 256>>>(w1,  whi + W1_OFF,  wlo + W1_OFF,  (int)(W1SZ / 4));
    split_w_kernel<<<49152, 256>>>(w2,  whi + W2_OFF,  wlo + W2_OFF,  (int)(W1SZ / 4));
    split_w_kernel<<<32000, 256>>>(wlm, whi + WLM_OFF, wlo + WLM_OFF, 8192000);

    embed_kernel<<<BT, 256>>>(idx, tok, pos, x);

    const dim3 gQkv (QKVLD / BN, BT / BM);  // (24,16)
    const dim3 gProj(CC / BN, BT / BM);     // (8,16)
    const dim3 gMlp1(FF / BN, BT / BM);     // (32,16)
    const dim3 gLm  (VV / BN, BT / BM);     // (250,16)
    const dim3 gAtt (4, BH);

    for (int l = 0; l < NL; l++) {
        size_t o3 = (size_t)l * 3145728;
        size_t oo = WO_OFF + (size_t)l * 1048576;
        size_t o1 = W1_OFF + (size_t)l * 4194304;
        size_t o2 = W2_OFF + (size_t)l * 4194304;

        ln_kernel<<<BT, 256>>>(x, xnh, xnl, ln1g + l * CC, ln1b + l * CC);
        bgemm_kernel<1><<<gQkv, 256, GEMM_SMEM>>>(BT, QKVLD, CC, xnh, xnl,
                                                  whi + o3, wlo + o3,
                                                  nullptr, qkvh, qkvl, nullptr, nullptr);
        attn_kernel<<<gAtt, 256, ATTN_SMEM>>>(qkvh, qkvl, yh, yl);
        bgemm_kernel<3><<<gProj, 256, GEMM_SMEM>>>(BT, CC, CC, yh, yl,
                                                   whi + oo, wlo + oo,
                                                   x, nullptr, nullptr, bo + l * CC, x);
        ln_kernel<<<BT, 256>>>(x, xnh, xnl, ln2g + l * CC, ln2b + l * CC);
        bgemm_kernel<2><<<gMlp1, 256, GEMM_SMEM>>>(BT, FF, CC, xnh, xnl,
                                                   whi + o1, wlo + o1,
                                                   nullptr, hh, hl, b1 + l * FF, nullptr);
        bgemm_kernel<3><<<gProj, 256, GEMM_SMEM>>>(BT, CC, FF, hh, hl,
                                                   whi + o2, wlo + o2,
                                                   x, nullptr, nullptr, b2 + l * CC, x);
    }

    ln_kernel<<<BT, 256>>>(x, xnh, xnl, lnfg, lnfb);
    bgemm_kernel<0><<<gLm, 256, GEMM_SMEM>>>(BT, VV, CC, xnh, xnl,
                                             whi + WLM_OFF, wlo + WLM_OFF,
                                             out, nullptr, nullptr, nullptr, nullptr);
}